// round 1
// baseline (speedup 1.0000x reference)
#include <cuda_runtime.h>
#include <math.h>

#define BB 4
#define AA 1024
#define NN 64
#define SS 50
#define FF 128
#define ROWS (BB*AA)   // 4096

// Scratch (device globals: allocation-free per harness rules)
__device__ float g_y[ROWS*FF];      // in2f projection  y = x @ W_in2f
__device__ float g_ysum[ROWS*FF];   // neighbor-summed conv output
__device__ float g_t[ROWS*FF];      // f2out intermediate
__device__ int   g_nbr_is64;        // neighbors dtype flag (1 = int64 layout)

__device__ __forceinline__ float sspf(float x) {
    // shifted softplus: log1p(exp(-|x|)) + max(x,0) - ln(2)   (matches jax.nn.softplus)
    return fmaxf(x, 0.0f) + log1pf(expf(-fabsf(x))) - 0.69314718055994531f;
}

// ---------------------------------------------------------------------------
// Detect whether the neighbors buffer is int64 or int32.
// Values are uniform in [0,1024). If int64 (little-endian), every odd int32
// word of the first 128 pairs is 0. Under int32, P(all 128 sampled words == 0)
// = (1/1024)^128 ~ 0. Deterministic given fixed inputs.
// ---------------------------------------------------------------------------
__global__ void detect_nbr_dtype_kernel(const int* __restrict__ nbr_raw) {
    if (threadIdx.x == 0 && blockIdx.x == 0) {
        int all_zero = 1;
        #pragma unroll 8
        for (int i = 0; i < 128; i++) {
            if (nbr_raw[2*i + 1] != 0) { all_zero = 0; break; }
        }
        g_nbr_is64 = all_zero;
    }
}

// ---------------------------------------------------------------------------
// Generic  C[M,128] = act(A[M,128] @ Bw[128,128] + bias)
// 256 threads/block, 64 rows/block. Thread tile 8(rows) x 4(cols).
// Dynamic smem: sA 64*128 + sB 128*128 floats = 98304 B.
// ACT: 0 = identity, 1 = shifted softplus.
// ---------------------------------------------------------------------------
template<int ACT>
__global__ void __launch_bounds__(256, 2)
gemm128_kernel(const float* __restrict__ A, const float* __restrict__ Bw,
               const float* __restrict__ bias, float* __restrict__ C, int M)
{
    extern __shared__ float sm[];
    float* sA = sm;             // 64*128
    float* sB = sm + 64*128;    // 128*128
    const int tid = threadIdx.x;
    const int m0  = blockIdx.x * 64;

    {
        const float4* Ag  = (const float4*)(A + (size_t)m0 * 128);
        float4*       sA4 = (float4*)sA;
        #pragma unroll
        for (int i = tid; i < 64*128/4; i += 256) sA4[i] = Ag[i];
        const float4* Bg  = (const float4*)Bw;
        float4*       sB4 = (float4*)sB;
        #pragma unroll
        for (int i = tid; i < 128*128/4; i += 256) sB4[i] = Bg[i];
    }
    __syncthreads();

    const int gcol = tid & 31;      // 32 column-groups of 4
    const int rrow = tid >> 5;      // 8 row-groups of 8
    const int g0   = gcol * 4;
    const int r0   = rrow * 8;

    float acc[8][4];
    #pragma unroll
    for (int i = 0; i < 8; i++) {
        #pragma unroll
        for (int j = 0; j < 4; j++)
            acc[i][j] = bias ? bias[g0 + j] : 0.0f;
    }

    #pragma unroll 4
    for (int k = 0; k < 128; k++) {
        const float4 bv = ((const float4*)(sB + k*128))[gcol];
        #pragma unroll
        for (int i = 0; i < 8; i++) {
            const float a = sA[(r0 + i)*128 + k];   // broadcast within warp
            acc[i][0] = fmaf(a, bv.x, acc[i][0]);
            acc[i][1] = fmaf(a, bv.y, acc[i][1]);
            acc[i][2] = fmaf(a, bv.z, acc[i][2]);
            acc[i][3] = fmaf(a, bv.w, acc[i][3]);
        }
    }

    #pragma unroll
    for (int i = 0; i < 8; i++) {
        float4 o;
        if (ACT == 1) {
            o.x = sspf(acc[i][0]); o.y = sspf(acc[i][1]);
            o.z = sspf(acc[i][2]); o.w = sspf(acc[i][3]);
        } else {
            o.x = acc[i][0]; o.y = acc[i][1]; o.z = acc[i][2]; o.w = acc[i][3];
        }
        ((float4*)(C + (size_t)(m0 + r0 + i)*128))[gcol] = o;
    }
}

// ---------------------------------------------------------------------------
// Main interaction kernel. One block per (b,a) atom; 256 threads.
//
// Dynamic smem layout (floats):
//   Region A  [0, 9600):
//     phase 0/1:  sWf1 [0,6400)   (50x128)
//                 sFij [6400,9600) (64x50)
//     phase 2+:   sH   [0,8192)   (64x128)       <-- overlays Wf1/Fij
//                 sRed [8192,9216) (8x128)
//   Region B  [9600, 25984):  sWf2 (128x128)
// Total 25984 floats = 103936 B  -> 2 blocks/SM.
// ---------------------------------------------------------------------------
__global__ void __launch_bounds__(256, 2)
interaction_kernel(const float* __restrict__ r_ij,
                   const void*  __restrict__ nbrs_raw,
                   const float* __restrict__ mask,
                   const float* __restrict__ f_ij,
                   const float* __restrict__ Wf1, const float* __restrict__ bf1,
                   const float* __restrict__ Wf2, const float* __restrict__ bf2,
                   const float* __restrict__ y_in, float* __restrict__ ysum_out)
{
    extern __shared__ float sm[];
    float* sWf1 = sm;
    float* sFij = sm + 6400;
    float* sH   = sm;            // overlays Wf1+Fij after phase 1
    float* sRed = sm + 8192;
    float* sWf2 = sm + 9600;
    __shared__ float sCw[NN];
    __shared__ int   sNbr[NN];

    const int tid = threadIdx.x;
    const int ba  = blockIdx.x;               // b*1024 + a
    const int is64 = g_nbr_is64;

    // ---- phase 0: stage weights + per-atom data ----
    {
        const float4* W2g = (const float4*)Wf2;
        float4*       s4  = (float4*)sWf2;
        #pragma unroll
        for (int i = tid; i < 128*128/4; i += 256) s4[i] = W2g[i];

        const float4* W1g = (const float4*)Wf1;
        float4*       s1  = (float4*)sWf1;
        #pragma unroll
        for (int i = tid; i < SS*128/4; i += 256) s1[i] = W1g[i];

        const float4* Fg = (const float4*)(f_ij + (size_t)ba * NN * SS);
        float4*       sf = (float4*)sFij;
        #pragma unroll
        for (int i = tid; i < NN*SS/4; i += 256) sf[i] = Fg[i];
    }
    if (tid < NN) {
        const size_t off = (size_t)ba * NN + tid;
        const float r = r_ij[off];
        const float c = (r < 5.0f)
            ? 0.5f * (cosf(r * 0.62831853071795864769f) + 1.0f)   // pi/5
            : 0.0f;
        sCw[tid]  = c * mask[off];
        sNbr[tid] = is64 ? (int)((const long long*)nbrs_raw)[off]
                         : ((const int*)nbrs_raw)[off];
    }
    __syncthreads();

    const int gcol = tid & 31;
    const int nrow = tid >> 5;
    const int g0   = gcol * 4;      // filter column base
    const int n0   = nrow * 8;      // neighbor row base

    // ---- phase 1: H[64,128] = ssp(Fij[64,50] @ Wf1[50,128] + bf1) ----
    float acc[8][4];
    #pragma unroll
    for (int i = 0; i < 8; i++) {
        #pragma unroll
        for (int j = 0; j < 4; j++) acc[i][j] = bf1[g0 + j];
    }
    #pragma unroll 2
    for (int s = 0; s < SS; s++) {
        const float4 bv = ((const float4*)(sWf1 + s*128))[gcol];
        #pragma unroll
        for (int i = 0; i < 8; i++) {
            const float a = sFij[(n0 + i)*SS + s];
            acc[i][0] = fmaf(a, bv.x, acc[i][0]);
            acc[i][1] = fmaf(a, bv.y, acc[i][1]);
            acc[i][2] = fmaf(a, bv.z, acc[i][2]);
            acc[i][3] = fmaf(a, bv.w, acc[i][3]);
        }
    }
    __syncthreads();   // everyone done reading sWf1/sFij before overlaying sH
    #pragma unroll
    for (int i = 0; i < 8; i++) {
        float4 h;
        h.x = sspf(acc[i][0]); h.y = sspf(acc[i][1]);
        h.z = sspf(acc[i][2]); h.w = sspf(acc[i][3]);
        ((float4*)(sH + (n0 + i)*128))[gcol] = h;
    }
    __syncthreads();

    // ---- phase 2: W[64,128] = H @ Wf2 + bf2 ----
    #pragma unroll
    for (int i = 0; i < 8; i++) {
        #pragma unroll
        for (int j = 0; j < 4; j++) acc[i][j] = bf2[g0 + j];
    }
    #pragma unroll 4
    for (int k = 0; k < 128; k++) {
        const float4 bv = ((const float4*)(sWf2 + k*128))[gcol];
        #pragma unroll
        for (int i = 0; i < 8; i++) {
            const float a = sH[(n0 + i)*128 + k];
            acc[i][0] = fmaf(a, bv.x, acc[i][0]);
            acc[i][1] = fmaf(a, bv.y, acc[i][1]);
            acc[i][2] = fmaf(a, bv.z, acc[i][2]);
            acc[i][3] = fmaf(a, bv.w, acc[i][3]);
        }
    }

    // ---- phase 3: apply cutoff*mask, gather y[neighbor], weighted partials ----
    const int brow_base = ba & ~(AA - 1);     // b * 1024
    float po0 = 0.f, po1 = 0.f, po2 = 0.f, po3 = 0.f;
    #pragma unroll
    for (int i = 0; i < 8; i++) {
        const int   n  = n0 + i;
        const float cw = sCw[n];
        const int   yr = brow_base + sNbr[n];
        const float4 y4 = ((const float4*)(y_in + (size_t)yr * 128))[gcol];
        po0 = fmaf(acc[i][0] * cw, y4.x, po0);
        po1 = fmaf(acc[i][1] * cw, y4.y, po1);
        po2 = fmaf(acc[i][2] * cw, y4.z, po2);
        po3 = fmaf(acc[i][3] * cw, y4.w, po3);
    }

    // ---- phase 4: reduce the 8 neighbor-row groups ----
    ((float4*)(sRed + nrow*128))[gcol] = make_float4(po0, po1, po2, po3);
    __syncthreads();
    if (tid < 128) {
        float s = 0.f;
        #pragma unroll
        for (int r = 0; r < 8; r++) s += sRed[r*128 + tid];
        ysum_out[(size_t)ba * 128 + tid] = s;
    }
}

// ---------------------------------------------------------------------------
extern "C" void kernel_launch(void* const* d_in, const int* in_sizes, int n_in,
                              void* d_out, int out_size)
{
    const float* x       = (const float*)d_in[0];
    const float* r_ij    = (const float*)d_in[1];
    const void*  nbrs    = d_in[2];                 // int32 or int64, detected on device
    const float* mask    = (const float*)d_in[3];
    const float* f_ij    = (const float*)d_in[4];
    const float* Wf1     = (const float*)d_in[5];
    const float* bf1     = (const float*)d_in[6];
    const float* Wf2     = (const float*)d_in[7];
    const float* bf2     = (const float*)d_in[8];
    const float* W_in2f  = (const float*)d_in[9];
    const float* W_f2out = (const float*)d_in[10];
    const float* b_f2out = (const float*)d_in[11];
    const float* W_dense = (const float*)d_in[12];
    const float* b_dense = (const float*)d_in[13];
    float* out = (float*)d_out;

    float *yp, *ysump, *tp;
    cudaGetSymbolAddress((void**)&yp,    g_y);
    cudaGetSymbolAddress((void**)&ysump, g_ysum);
    cudaGetSymbolAddress((void**)&tp,    g_t);

    const int GEMM_SMEM = 98304;
    const int MAIN_SMEM = 103936;
    cudaFuncSetAttribute(gemm128_kernel<0>, cudaFuncAttributeMaxDynamicSharedMemorySize, GEMM_SMEM);
    cudaFuncSetAttribute(gemm128_kernel<1>, cudaFuncAttributeMaxDynamicSharedMemorySize, GEMM_SMEM);
    cudaFuncSetAttribute(interaction_kernel, cudaFuncAttributeMaxDynamicSharedMemorySize, MAIN_SMEM);

    // 0) neighbor dtype probe (deterministic)
    detect_nbr_dtype_kernel<<<1, 32>>>((const int*)nbrs);

    // 1) y = x @ W_in2f                       [4096,128]
    gemm128_kernel<0><<<ROWS/64, 256, GEMM_SMEM>>>(x, W_in2f, nullptr, yp, ROWS);

    // 2) filter net + cutoff + gather + neighbor-sum  -> g_ysum
    interaction_kernel<<<ROWS, 256, MAIN_SMEM>>>(r_ij, nbrs, mask, f_ij,
                                                 Wf1, bf1, Wf2, bf2, yp, ysump);

    // 3) t = ssp(ysum @ W_f2out + b_f2out)
    gemm128_kernel<1><<<ROWS/64, 256, GEMM_SMEM>>>(ysump, W_f2out, b_f2out, tp, ROWS);

    // 4) out = t @ W_dense + b_dense
    gemm128_kernel<0><<<ROWS/64, 256, GEMM_SMEM>>>(tp, W_dense, b_dense, out, ROWS);
}

// round 4
// speedup vs baseline: 1.7564x; 1.7564x over previous
#include <cuda_runtime.h>
#include <cstdint>
#include <math.h>

#define BB 4
#define AA 1024
#define SS 50
#define ROWS (BB*AA)   // 4096
#define ITERS (ROWS/2) // 2048 iterations x 2 atoms

// Scratch
__device__ float g_y[ROWS*128];
__device__ float g_ysum[ROWS*128];
__device__ float g_t[ROWS*128];
__device__ int   g_nbr_is64;

// ---------------------------------------------------------------------------
__device__ __forceinline__ float tf32f(float x) {
    uint32_t r; asm("cvt.rna.tf32.f32 %0, %1;" : "=r"(r) : "f"(x));
    return __uint_as_float(r);
}
__device__ __forceinline__ float sspf(float x) {
    float e = __expf(-fabsf(x));
    return fmaxf(x, 0.0f) + __log2f(1.0f + e) * 0.69314718055994531f - 0.69314718055994531f;
}
#define MMA_TF32(d, a0, a1, a2, a3, b0, b1) \
    asm volatile("mma.sync.aligned.m16n8k8.row.col.f32.tf32.tf32.f32 " \
        "{%0,%1,%2,%3}, {%4,%5,%6,%7}, {%8,%9}, {%0,%1,%2,%3};" \
        : "+f"((d)[0]), "+f"((d)[1]), "+f"((d)[2]), "+f"((d)[3]) \
        : "r"(a0), "r"(a1), "r"(a2), "r"(a3), "r"(b0), "r"(b1))

// ---------------------------------------------------------------------------
__global__ void detect_nbr_dtype_kernel(const int* __restrict__ nbr_raw) {
    if (threadIdx.x == 0 && blockIdx.x == 0) {
        int all_zero = 1;
        for (int i = 0; i < 128; i++)
            if (nbr_raw[2*i + 1] != 0) { all_zero = 0; break; }
        g_nbr_is64 = all_zero;
    }
}

// ---------------------------------------------------------------------------
// Row GEMM: C[4096,128] = act(A @ B + bias). 512 threads, 64 rows/block.
// ---------------------------------------------------------------------------
template<int ACT>
__global__ void __launch_bounds__(512, 1)
gemm128_kernel(const float* __restrict__ A, const float* __restrict__ Bw,
               const float* __restrict__ bias, float* __restrict__ C)
{
    extern __shared__ float sm[];
    float* sA = sm;             // 64*128
    float* sB = sm + 64*128;    // 128*128
    const int tid = threadIdx.x;
    const int m0  = blockIdx.x * 64;
    {
        const float4* Ag = (const float4*)(A + (size_t)m0 * 128);
        float4* sA4 = (float4*)sA;
        for (int i = tid; i < 64*128/4; i += 512) sA4[i] = Ag[i];
        const float4* Bg = (const float4*)Bw;
        float4* sB4 = (float4*)sB;
        for (int i = tid; i < 128*128/4; i += 512) sB4[i] = Bg[i];
    }
    __syncthreads();
    const int gcol = tid & 31, rg = tid >> 5;
    const int g0 = gcol * 4, r0 = rg * 4;
    float acc[4][4];
    #pragma unroll
    for (int i = 0; i < 4; i++)
        #pragma unroll
        for (int j = 0; j < 4; j++) acc[i][j] = bias ? bias[g0 + j] : 0.0f;
    #pragma unroll 4
    for (int k = 0; k < 128; k++) {
        const float4 bv = ((const float4*)(sB + k*128))[gcol];
        #pragma unroll
        for (int i = 0; i < 4; i++) {
            const float a = sA[(r0 + i)*128 + k];
            acc[i][0] = fmaf(a, bv.x, acc[i][0]);
            acc[i][1] = fmaf(a, bv.y, acc[i][1]);
            acc[i][2] = fmaf(a, bv.z, acc[i][2]);
            acc[i][3] = fmaf(a, bv.w, acc[i][3]);
        }
    }
    #pragma unroll
    for (int i = 0; i < 4; i++) {
        float4 o;
        if (ACT == 1) { o.x=sspf(acc[i][0]); o.y=sspf(acc[i][1]); o.z=sspf(acc[i][2]); o.w=sspf(acc[i][3]); }
        else          { o.x=acc[i][0]; o.y=acc[i][1]; o.z=acc[i][2]; o.w=acc[i][3]; }
        ((float4*)(C + (size_t)(m0 + r0 + i)*128))[gcol] = o;
    }
}

// ---------------------------------------------------------------------------
// Persistent mma.sync tf32 interaction kernel. 148 blocks x 256 threads.
// Each iteration = 2 atoms (M = 128 neighbor-slot rows).
//
// Smem layout (float offsets):
//   sW2  [0, 16896)      Wf2^T  [n=128][k=128]  stride 132 (tf32)
//   sW1  [16896, 24576)  Wf1^T  [n=128][k<=56]  stride 60  (tf32, zero-pad)
//   sA1  [24576, 33280)  f_ij   [row=128][k<=56] stride 68 (tf32, zero-pad)
//   sH   [33280, 50176)  H tile [128][128] stride 132; overlaid by sProd
//   sCw  [50176, 50304)
//   sNbr [50304, 50432)
// Total 50432 floats = 201728 B.
// ---------------------------------------------------------------------------
#define ST_W2 132
#define ST_W1 60
#define ST_A1 68
#define ST_H  132
#define OFF_W1 16896
#define OFF_A1 24576
#define OFF_H  33280
#define OFF_CW 50176
#define OFF_NB 50304
#define MAIN_SMEM (50432*4)

__global__ void __launch_bounds__(256, 1)
interaction_mma_kernel(const float* __restrict__ r_ij,
                       const void*  __restrict__ nbrs_raw,
                       const float* __restrict__ mask,
                       const float* __restrict__ f_ij,
                       const float* __restrict__ Wf1, const float* __restrict__ bf1,
                       const float* __restrict__ Wf2, const float* __restrict__ bf2,
                       const float* __restrict__ y_in, float* __restrict__ ysum_out)
{
    extern __shared__ float sm[];
    float* sW2 = sm;
    float* sW1 = sm + OFF_W1;
    float* sA1 = sm + OFF_A1;
    float* sH  = sm + OFF_H;        // also sProd
    float* sCw = sm + OFF_CW;
    int*   sNbr = (int*)(sm + OFF_NB);

    const int tid  = threadIdx.x;
    const int w    = tid >> 5;
    const int lane = tid & 31;
    const int qr   = lane >> 2;     // 0..7
    const int qc   = lane & 3;      // 0..3
    const int is64 = g_nbr_is64;

    // ---- stage transposed weights once (tf32) ----
    for (int idx = tid; idx < 128*56; idx += 256) {
        int n = idx / 56, k = idx % 56;
        sW1[n*ST_W1 + k] = (k < SS) ? tf32f(Wf1[k*128 + n]) : 0.0f;
    }
    for (int idx = tid; idx < 128*128; idx += 256) {
        int n = idx >> 7, k = idx & 127;
        sW2[n*ST_W2 + k] = tf32f(Wf2[k*128 + n]);
    }
    __syncthreads();

    const int R0 = w*16 + qr;       // global tile row this thread owns
    const int R1 = R0 + 8;

    for (int it = blockIdx.x; it < ITERS; it += gridDim.x) {
        // ---- stage A1 = f_ij[128 rows][50] tf32, zero-pad to 56 ----
        const float* fb = f_ij + (size_t)it * 128 * SS;
        for (int idx = tid; idx < 128*28; idx += 256) {
            int row = idx / 28, j = idx % 28;
            float2 v;
            if (j < 25) v = *(const float2*)(fb + row*SS + 2*j);
            else        v = make_float2(0.0f, 0.0f);
            sA1[row*ST_A1 + 2*j]     = tf32f(v.x);
            sA1[row*ST_A1 + 2*j + 1] = tf32f(v.y);
        }
        if (tid < 128) {
            const size_t off = (size_t)it * 128 + tid;
            const float r = r_ij[off];
            const float c = (r < 5.0f) ? 0.5f * (cosf(r * 0.62831853071795864769f) + 1.0f) : 0.0f;
            sCw[tid]  = c * mask[off];
            sNbr[tid] = is64 ? (int)((const long long*)nbrs_raw)[off]
                             : ((const int*)nbrs_raw)[off];
        }
        __syncthreads();

        // ---- MMA1: acc = Fij @ Wf1 + bf1   (K = 56) ----
        float acc[16][4];
        #pragma unroll
        for (int n = 0; n < 16; n++) {
            const float2 b2 = *(const float2*)(bf1 + 8*n + 2*qc);
            acc[n][0] = b2.x; acc[n][1] = b2.y;
            acc[n][2] = b2.x; acc[n][3] = b2.y;
        }
        #pragma unroll 1
        for (int kt = 0; kt < 7; kt++) {
            const int kb = kt * 8;
            const uint32_t a0 = __float_as_uint(sA1[R0*ST_A1 + kb + qc]);
            const uint32_t a1 = __float_as_uint(sA1[R1*ST_A1 + kb + qc]);
            const uint32_t a2 = __float_as_uint(sA1[R0*ST_A1 + kb + qc + 4]);
            const uint32_t a3 = __float_as_uint(sA1[R1*ST_A1 + kb + qc + 4]);
            #pragma unroll
            for (int n = 0; n < 16; n++) {
                const uint32_t b0 = __float_as_uint(sW1[(8*n + qr)*ST_W1 + kb + qc]);
                const uint32_t b1 = __float_as_uint(sW1[(8*n + qr)*ST_W1 + kb + qc + 4]);
                MMA_TF32(acc[n], a0, a1, a2, a3, b0, b1);
            }
        }

        // ---- H = ssp(acc) -> smem (tf32). Own-warp rows only. ----
        #pragma unroll
        for (int n = 0; n < 16; n++) {
            const int c = 8*n + 2*qc;
            *(float2*)(sH + R0*ST_H + c) =
                make_float2(tf32f(sspf(acc[n][0])), tf32f(sspf(acc[n][1])));
            *(float2*)(sH + R1*ST_H + c) =
                make_float2(tf32f(sspf(acc[n][2])), tf32f(sspf(acc[n][3])));
        }
        __syncwarp();

        // ---- MMA2: acc = H @ Wf2 + bf2   (K = 128) ----
        #pragma unroll
        for (int n = 0; n < 16; n++) {
            const float2 b2 = *(const float2*)(bf2 + 8*n + 2*qc);
            acc[n][0] = b2.x; acc[n][1] = b2.y;
            acc[n][2] = b2.x; acc[n][3] = b2.y;
        }
        #pragma unroll 1
        for (int kt = 0; kt < 16; kt++) {
            const int kb = kt * 8;
            const uint32_t a0 = __float_as_uint(sH[R0*ST_H + kb + qc]);
            const uint32_t a1 = __float_as_uint(sH[R1*ST_H + kb + qc]);
            const uint32_t a2 = __float_as_uint(sH[R0*ST_H + kb + qc + 4]);
            const uint32_t a3 = __float_as_uint(sH[R1*ST_H + kb + qc + 4]);
            #pragma unroll
            for (int n = 0; n < 16; n++) {
                const uint32_t b0 = __float_as_uint(sW2[(8*n + qr)*ST_W2 + kb + qc]);
                const uint32_t b1 = __float_as_uint(sW2[(8*n + qr)*ST_W2 + kb + qc + 4]);
                MMA_TF32(acc[n], a0, a1, a2, a3, b0, b1);
            }
        }
        __syncwarp();   // all lanes done reading sH strip before overwriting as sProd

        // ---- epilogue: prod = acc * cw[row] * y[nbr[row]][col] -> sProd(=sH) ----
        {
            const int base = ((2*it) >> 10) << 10;   // batch * 1024
            const float cw0 = sCw[R0], cw1 = sCw[R1];
            const float* y0r = y_in + (size_t)(base + sNbr[R0]) * 128;
            const float* y1r = y_in + (size_t)(base + sNbr[R1]) * 128;
            #pragma unroll
            for (int n = 0; n < 16; n++) {
                const int c = 8*n + 2*qc;
                const float2 y0 = *(const float2*)(y0r + c);
                const float2 y1 = *(const float2*)(y1r + c);
                *(float2*)(sH + R0*ST_H + c) =
                    make_float2(acc[n][0]*cw0*y0.x, acc[n][1]*cw0*y0.y);
                *(float2*)(sH + R1*ST_H + c) =
                    make_float2(acc[n][2]*cw1*y1.x, acc[n][3]*cw1*y1.y);
            }
        }
        __syncthreads();

        // ---- reduce 64 neighbor rows per atom ----
        {
            const int al = tid >> 7, g = tid & 127;
            const float* p = sH + (size_t)(al*64)*ST_H + g;
            float s = 0.0f;
            #pragma unroll
            for (int n2 = 0; n2 < 64; n2++) s += p[(size_t)n2 * ST_H];
            ysum_out[(size_t)(2*it + al)*128 + g] = s;
        }
        __syncthreads();
    }
}

// ---------------------------------------------------------------------------
extern "C" void kernel_launch(void* const* d_in, const int* in_sizes, int n_in,
                              void* d_out, int out_size)
{
    const float* x       = (const float*)d_in[0];
    const float* r_ij    = (const float*)d_in[1];
    const void*  nbrs    = d_in[2];
    const float* mask    = (const float*)d_in[3];
    const float* f_ij    = (const float*)d_in[4];
    const float* Wf1     = (const float*)d_in[5];
    const float* bf1     = (const float*)d_in[6];
    const float* Wf2     = (const float*)d_in[7];
    const float* bf2     = (const float*)d_in[8];
    const float* W_in2f  = (const float*)d_in[9];
    const float* W_f2out = (const float*)d_in[10];
    const float* b_f2out = (const float*)d_in[11];
    const float* W_dense = (const float*)d_in[12];
    const float* b_dense = (const float*)d_in[13];
    float* out = (float*)d_out;

    float *yp, *ysump, *tp;
    cudaGetSymbolAddress((void**)&yp,    g_y);
    cudaGetSymbolAddress((void**)&ysump, g_ysum);
    cudaGetSymbolAddress((void**)&tp,    g_t);

    const int GEMM_SMEM = 98304;
    cudaFuncSetAttribute(gemm128_kernel<0>, cudaFuncAttributeMaxDynamicSharedMemorySize, GEMM_SMEM);
    cudaFuncSetAttribute(gemm128_kernel<1>, cudaFuncAttributeMaxDynamicSharedMemorySize, GEMM_SMEM);
    cudaFuncSetAttribute(interaction_mma_kernel, cudaFuncAttributeMaxDynamicSharedMemorySize, MAIN_SMEM);

    detect_nbr_dtype_kernel<<<1, 32>>>((const int*)nbrs);

    gemm128_kernel<0><<<ROWS/64, 512, GEMM_SMEM>>>(x, W_in2f, nullptr, yp);

    interaction_mma_kernel<<<148, 256, MAIN_SMEM>>>(r_ij, nbrs, mask, f_ij,
                                                    Wf1, bf1, Wf2, bf2, yp, ysump);

    gemm128_kernel<1><<<ROWS/64, 512, GEMM_SMEM>>>(ysump, W_f2out, b_f2out, tp);
    gemm128_kernel<0><<<ROWS/64, 512, GEMM_SMEM>>>(tp, W_dense, b_dense, out);
}

// round 6
// speedup vs baseline: 2.8077x; 1.5985x over previous
#include <cuda_runtime.h>
#include <cuda_fp16.h>
#include <cstdint>
#include <math.h>

#define SS 50
#define ROWS 4096
#define ITERS 2048           // 2 atoms / iter

// Scratch
__device__ float g_y[ROWS*128];
__device__ float g_ysum[ROWS*128];
__device__ float g_t[ROWS*128];
__device__ int   g_nbr_is64;

// ---------------------------------------------------------------------------
__device__ __forceinline__ float sspf(float x) {
    float e = __expf(-fabsf(x));
    return fmaxf(x, 0.0f) + __log2f(1.0f + e) * 0.69314718055994531f - 0.69314718055994531f;
}
__device__ __forceinline__ uint32_t h2(float a, float b) {
    __half2 h = __floats2half2_rn(a, b);
    return *reinterpret_cast<uint32_t*>(&h);
}
// position of half2-index k2 inside a k-chunk-paired row: pairs (k2, k2+4) adjacent
__device__ __forceinline__ uint32_t pos2(uint32_t k2) {
    return (k2 & ~7u) + ((k2 & 3u) << 1) + ((k2 >> 2) & 1u);
}
#define MMA_F16(d, a0, a1, a2, a3, b0, b1) \
    asm volatile("mma.sync.aligned.m16n8k16.row.col.f32.f16.f16.f32 " \
        "{%0,%1,%2,%3}, {%4,%5,%6,%7}, {%8,%9}, {%0,%1,%2,%3};" \
        : "+f"((d)[0]), "+f"((d)[1]), "+f"((d)[2]), "+f"((d)[3]) \
        : "r"(a0), "r"(a1), "r"(a2), "r"(a3), "r"(b0), "r"(b1))

// ---------------------------------------------------------------------------
__global__ void detect_nbr_dtype_kernel(const int* __restrict__ nbr_raw) {
    if (threadIdx.x == 0 && blockIdx.x == 0) {
        int all_zero = 1;
        for (int i = 0; i < 128; i++)
            if (nbr_raw[2*i + 1] != 0) { all_zero = 0; break; }
        g_nbr_is64 = all_zero;
    }
}

// ---------------------------------------------------------------------------
// Row GEMM: C[4096,128] = act(A@B + bias). M=32/block -> grid 128 (occupancy fix).
// ---------------------------------------------------------------------------
template<int ACT>
__global__ void __launch_bounds__(256, 1)
gemm32_kernel(const float* __restrict__ A, const float* __restrict__ Bw,
              const float* __restrict__ bias, float* __restrict__ C)
{
    extern __shared__ float sm[];
    float* sA = sm;             // 32*128
    float* sB = sm + 32*128;    // 128*128
    const int tid = threadIdx.x;
    const int m0  = blockIdx.x * 32;
    {
        const float4* Ag = (const float4*)(A + (size_t)m0 * 128);
        float4* sA4 = (float4*)sA;
        #pragma unroll
        for (int i = tid; i < 32*128/4; i += 256) sA4[i] = Ag[i];
        const float4* Bg = (const float4*)Bw;
        float4* sB4 = (float4*)sB;
        #pragma unroll
        for (int i = tid; i < 128*128/4; i += 256) sB4[i] = Bg[i];
    }
    __syncthreads();
    const int gcol = tid & 31, rg = tid >> 5;
    const int g0 = gcol * 4, r0 = rg * 4;
    float acc[4][4];
    #pragma unroll
    for (int i = 0; i < 4; i++)
        #pragma unroll
        for (int j = 0; j < 4; j++) acc[i][j] = bias ? bias[g0 + j] : 0.0f;
    #pragma unroll 4
    for (int k = 0; k < 128; k++) {
        const float4 bv = ((const float4*)(sB + k*128))[gcol];
        #pragma unroll
        for (int i = 0; i < 4; i++) {
            const float a = sA[(r0 + i)*128 + k];
            acc[i][0] = fmaf(a, bv.x, acc[i][0]);
            acc[i][1] = fmaf(a, bv.y, acc[i][1]);
            acc[i][2] = fmaf(a, bv.z, acc[i][2]);
            acc[i][3] = fmaf(a, bv.w, acc[i][3]);
        }
    }
    #pragma unroll
    for (int i = 0; i < 4; i++) {
        float4 o;
        if (ACT == 1) { o.x=sspf(acc[i][0]); o.y=sspf(acc[i][1]); o.z=sspf(acc[i][2]); o.w=sspf(acc[i][3]); }
        else          { o.x=acc[i][0]; o.y=acc[i][1]; o.z=acc[i][2]; o.w=acc[i][3]; }
        ((float4*)(C + (size_t)(m0 + r0 + i)*128))[gcol] = o;
    }
}
#define GEMM_SMEM ((32*128 + 128*128)*4)

// ---------------------------------------------------------------------------
// Persistent fp16 mma.sync interaction kernel. 148 blocks x 256 threads.
// Per iteration: 2 atoms -> M=128 neighbor rows; warps tiled 4(M) x 2(N).
//
// Smem (uint32 word offsets):
//   W2H  [0, 9216)       Wf2^T half2-paired  [n=128][k2=64] stride 72
//   W1H  [9216, 14336)   Wf1^T half2-paired  [n=128][k2<=25 pad 32] stride 40
//   A1H  [14336, 19456)  f_ij  half2-paired  [row=128][k2 pad 32] stride 40
//   HH   [19456, 28672)  H     half2-paired  [row=128][k2=64] stride 72
//   PROD [28672, 45568)  fp32 prod [128][stride 132]
//   CW   [45568, 45824)  2 x 128 fp32 (double buffer)
//   NB   [45824, 46080)  2 x 128 int
// Total 46080 words = 184320 B.
// ---------------------------------------------------------------------------
#define W2H   0u
#define W1H   9216u
#define A1H   14336u
#define HH    19456u
#define PRODO 28672u
#define CWO   45568u
#define NBO   45824u
#define MAIN_SMEM (46080*4)

__global__ void __launch_bounds__(256, 1)
interaction_f16_kernel(const float* __restrict__ r_ij,
                       const void*  __restrict__ nbrs_raw,
                       const float* __restrict__ mask,
                       const float* __restrict__ f_ij,
                       const float* __restrict__ Wf1, const float* __restrict__ bf1,
                       const float* __restrict__ Wf2, const float* __restrict__ bf2,
                       const float* __restrict__ y_in, float* __restrict__ ysum_out)
{
    extern __shared__ uint32_t smw[];
    float* sProd = (float*)(smw + PRODO);
    float* sCw   = (float*)(smw + CWO);
    int*   sNbr  = (int*)(smw + NBO);

    const int tid  = threadIdx.x;
    const int w    = tid >> 5;
    const int lane = tid & 31;
    const int qr   = lane >> 2;
    const int qc   = lane & 3;
    const int wm   = w & 3;        // M tile: rows wm*32..+31
    const int wn   = w >> 2;       // N tile: cols wn*64..+63
    const int is64 = g_nbr_is64;

    // ---- stage weights once (half2, k-paired) ----
    for (int idx = tid; idx < 128*64; idx += 256) {
        int n = idx >> 6, k2 = idx & 63;
        smw[W2H + n*72 + pos2(k2)] = h2(Wf2[(2*k2)*128 + n], Wf2[(2*k2+1)*128 + n]);
    }
    for (int idx = tid; idx < 128*32; idx += 256) {
        int n = idx >> 5, k2 = idx & 31;
        float v0 = (2*k2     < SS) ? Wf1[(2*k2)*128 + n]   : 0.0f;
        float v1 = (2*k2 + 1 < SS) ? Wf1[(2*k2+1)*128 + n] : 0.0f;
        smw[W1H + n*40 + pos2(k2)] = h2(v0, v1);
    }
    // zero A1 pad region (k2 25..31) once
    for (int idx = tid; idx < 128*7; idx += 256) {
        int row = idx / 7, k2 = 25 + idx % 7;
        smw[A1H + row*40 + pos2(k2)] = 0u;
    }
    // ---- stage first iteration's A1 + cw/nbr (buffer 0) ----
    {
        const int it0 = blockIdx.x;
        const float* fb = f_ij + (size_t)it0 * 6400;
        for (int idx = tid; idx < 3200; idx += 256) {
            int row = idx / 25, k2 = idx % 25;
            float2 v = *(const float2*)(fb + row*SS + 2*k2);
            smw[A1H + row*40 + pos2(k2)] = h2(v.x, v.y);
        }
        if (tid < 128) {
            size_t off = (size_t)it0 * 128 + tid;
            float r = r_ij[off];
            float c = (r < 5.0f) ? 0.5f*(cosf(r*0.62831853071795864769f)+1.0f) : 0.0f;
            sCw[tid]  = c * mask[off];
            sNbr[tid] = is64 ? (int)((const long long*)nbrs_raw)[off]
                             : ((const int*)nbrs_raw)[off];
        }
    }
    __syncthreads();

    const int r0 = wm*32 + qr;          // rows r0, r0+8, r0+16, r0+24
    int p = 0;
    for (int it = blockIdx.x; it < ITERS; it += gridDim.x) {
        const int  nxt = it + gridDim.x;
        const bool hasNext = nxt < ITERS;

        // ---- prefetch next iter's inputs into registers (overlaps MMAs) ----
        float2 pf[13];
        if (hasNext) {
            const float* fb = f_ij + (size_t)nxt * 6400;
            #pragma unroll
            for (int j = 0; j < 13; j++) {
                int idx = tid + j*256;
                if (idx < 3200) {
                    int row = idx / 25, k2 = idx % 25;
                    pf[j] = *(const float2*)(fb + row*SS + 2*k2);
                }
            }
        }
        float nr = 0.f, nm = 0.f; int nn = 0;
        if (hasNext && tid < 128) {
            size_t off = (size_t)nxt * 128 + tid;
            nr = r_ij[off]; nm = mask[off];
            nn = is64 ? (int)((const long long*)nbrs_raw)[off]
                      : ((const int*)nbrs_raw)[off];
        }

        // ---- MMA1: H' = Fij @ Wf1 + bf1   (K=64 padded, 4 k16 chunks) ----
        float acc[2][8][4];
        #pragma unroll
        for (int n = 0; n < 8; n++) {
            const float2 b2 = *(const float2*)(bf1 + wn*64 + 8*n + 2*qc);
            #pragma unroll
            for (int mt = 0; mt < 2; mt++) {
                acc[mt][n][0] = b2.x; acc[mt][n][1] = b2.y;
                acc[mt][n][2] = b2.x; acc[mt][n][3] = b2.y;
            }
        }
        #pragma unroll
        for (int kt = 0; kt < 4; kt++) {
            const int ko = kt*8 + 2*qc;
            const uint2 aA0 = *(const uint2*)(smw + A1H + (r0     )*40 + ko);
            const uint2 aB0 = *(const uint2*)(smw + A1H + (r0 +  8)*40 + ko);
            const uint2 aA1 = *(const uint2*)(smw + A1H + (r0 + 16)*40 + ko);
            const uint2 aB1 = *(const uint2*)(smw + A1H + (r0 + 24)*40 + ko);
            #pragma unroll
            for (int n = 0; n < 8; n++) {
                const uint2 b = *(const uint2*)(smw + W1H + (wn*64 + 8*n + qr)*40 + ko);
                MMA_F16(acc[0][n], aA0.x, aB0.x, aA0.y, aB0.y, b.x, b.y);
                MMA_F16(acc[1][n], aA1.x, aB1.x, aA1.y, aB1.y, b.x, b.y);
            }
        }
        // ---- H = ssp(acc) -> HH (half2, paired) ----
        #pragma unroll
        for (int n = 0; n < 8; n++) {
            const uint32_t po = pos2((uint32_t)(wn*32 + 4*n + qc));
            smw[HH + (r0     )*72 + po] = h2(sspf(acc[0][n][0]), sspf(acc[0][n][1]));
            smw[HH + (r0 +  8)*72 + po] = h2(sspf(acc[0][n][2]), sspf(acc[0][n][3]));
            smw[HH + (r0 + 16)*72 + po] = h2(sspf(acc[1][n][0]), sspf(acc[1][n][1]));
            smw[HH + (r0 + 24)*72 + po] = h2(sspf(acc[1][n][2]), sspf(acc[1][n][3]));
        }
        __syncthreads();   // S1: H complete; A1 free

        // ---- drain prefetch: next A1 tile + cw/nbr (other buffer) ----
        if (hasNext) {
            #pragma unroll
            for (int j = 0; j < 13; j++) {
                int idx = tid + j*256;
                if (idx < 3200) {
                    int row = idx / 25, k2 = idx % 25;
                    smw[A1H + row*40 + pos2(k2)] = h2(pf[j].x, pf[j].y);
                }
            }
            if (tid < 128) {
                float c = (nr < 5.0f) ? 0.5f*(cosf(nr*0.62831853071795864769f)+1.0f) : 0.0f;
                sCw[(p^1)*128 + tid]  = c * nm;
                sNbr[(p^1)*128 + tid] = nn;
            }
        }

        // ---- MMA2: W = H @ Wf2 + bf2   (K=128, 8 k16 chunks) ----
        #pragma unroll
        for (int n = 0; n < 8; n++) {
            const float2 b2 = *(const float2*)(bf2 + wn*64 + 8*n + 2*qc);
            #pragma unroll
            for (int mt = 0; mt < 2; mt++) {
                acc[mt][n][0] = b2.x; acc[mt][n][1] = b2.y;
                acc[mt][n][2] = b2.x; acc[mt][n][3] = b2.y;
            }
        }
        #pragma unroll
        for (int kt = 0; kt < 8; kt++) {
            const int ko = kt*8 + 2*qc;
            const uint2 aA0 = *(const uint2*)(smw + HH + (r0     )*72 + ko);
            const uint2 aB0 = *(const uint2*)(smw + HH + (r0 +  8)*72 + ko);
            const uint2 aA1 = *(const uint2*)(smw + HH + (r0 + 16)*72 + ko);
            const uint2 aB1 = *(const uint2*)(smw + HH + (r0 + 24)*72 + ko);
            #pragma unroll
            for (int n = 0; n < 8; n++) {
                const uint2 b = *(const uint2*)(smw + W2H + (wn*64 + 8*n + qr)*72 + ko);
                MMA_F16(acc[0][n], aA0.x, aB0.x, aA0.y, aB0.y, b.x, b.y);
                MMA_F16(acc[1][n], aA1.x, aB1.x, aA1.y, aB1.y, b.x, b.y);
            }
        }

        // ---- epilogue: prod = acc * cw[row] * y[nbr[row]] -> sProd (fp32) ----
        {
            const int base = ((2*it) >> 10) << 10;    // batch * 1024
            const float cw0 = sCw[p*128 + r0],      cw1 = sCw[p*128 + r0 + 8];
            const float cw2 = sCw[p*128 + r0 + 16], cw3 = sCw[p*128 + r0 + 24];
            const float* y0 = y_in + (size_t)(base + sNbr[p*128 + r0     ]) * 128;
            const float* y1 = y_in + (size_t)(base + sNbr[p*128 + r0 +  8]) * 128;
            const float* y2 = y_in + (size_t)(base + sNbr[p*128 + r0 + 16]) * 128;
            const float* y3 = y_in + (size_t)(base + sNbr[p*128 + r0 + 24]) * 128;
            #pragma unroll
            for (int n = 0; n < 8; n++) {
                const int c = wn*64 + 8*n + 2*qc;
                const float2 v0 = *(const float2*)(y0 + c);
                const float2 v1 = *(const float2*)(y1 + c);
                const float2 v2 = *(const float2*)(y2 + c);
                const float2 v3 = *(const float2*)(y3 + c);
                *(float2*)(sProd + (r0     )*132 + c) = make_float2(acc[0][n][0]*cw0*v0.x, acc[0][n][1]*cw0*v0.y);
                *(float2*)(sProd + (r0 +  8)*132 + c) = make_float2(acc[0][n][2]*cw1*v1.x, acc[0][n][3]*cw1*v1.y);
                *(float2*)(sProd + (r0 + 16)*132 + c) = make_float2(acc[1][n][0]*cw2*v2.x, acc[1][n][1]*cw2*v2.y);
                *(float2*)(sProd + (r0 + 24)*132 + c) = make_float2(acc[1][n][2]*cw3*v3.x, acc[1][n][3]*cw3*v3.y);
            }
        }
        __syncthreads();   // S2

        // ---- reduce 64 neighbor rows per atom ----
        {
            const int al = tid >> 7, g = tid & 127;
            const float* pp = sProd + (size_t)(al*64)*132 + g;
            float s = 0.0f;
            #pragma unroll
            for (int n2 = 0; n2 < 64; n2++) s += pp[(size_t)n2 * 132];
            ysum_out[(size_t)(2*it + al)*128 + g] = s;
        }
        __syncthreads();   // S3
        p ^= 1;
    }
}

// ---------------------------------------------------------------------------
extern "C" void kernel_launch(void* const* d_in, const int* in_sizes, int n_in,
                              void* d_out, int out_size)
{
    const float* x       = (const float*)d_in[0];
    const float* r_ij    = (const float*)d_in[1];
    const void*  nbrs    = d_in[2];
    const float* mask    = (const float*)d_in[3];
    const float* f_ij    = (const float*)d_in[4];
    const float* Wf1     = (const float*)d_in[5];
    const float* bf1     = (const float*)d_in[6];
    const float* Wf2     = (const float*)d_in[7];
    const float* bf2     = (const float*)d_in[8];
    const float* W_in2f  = (const float*)d_in[9];
    const float* W_f2out = (const float*)d_in[10];
    const float* b_f2out = (const float*)d_in[11];
    const float* W_dense = (const float*)d_in[12];
    const float* b_dense = (const float*)d_in[13];
    float* out = (float*)d_out;

    float *yp, *ysump, *tp;
    cudaGetSymbolAddress((void**)&yp,    g_y);
    cudaGetSymbolAddress((void**)&ysump, g_ysum);
    cudaGetSymbolAddress((void**)&tp,    g_t);

    cudaFuncSetAttribute(gemm32_kernel<0>, cudaFuncAttributeMaxDynamicSharedMemorySize, GEMM_SMEM);
    cudaFuncSetAttribute(gemm32_kernel<1>, cudaFuncAttributeMaxDynamicSharedMemorySize, GEMM_SMEM);
    cudaFuncSetAttribute(interaction_f16_kernel, cudaFuncAttributeMaxDynamicSharedMemorySize, MAIN_SMEM);

    detect_nbr_dtype_kernel<<<1, 32>>>((const int*)nbrs);

    gemm32_kernel<0><<<ROWS/32, 256, GEMM_SMEM>>>(x, W_in2f, nullptr, yp);

    interaction_f16_kernel<<<148, 256, MAIN_SMEM>>>(r_ij, nbrs, mask, f_ij,
                                                    Wf1, bf1, Wf2, bf2, yp, ysump);

    gemm32_kernel<1><<<ROWS/32, 256, GEMM_SMEM>>>(ysump, W_f2out, b_f2out, tp);
    gemm32_kernel<0><<<ROWS/32, 256, GEMM_SMEM>>>(tp, W_dense, b_dense, out);
}